// round 8
// baseline (speedup 1.0000x reference)
#include <cuda_runtime.h>

#define FULL_MASK 0xFFFFFFFFu

// Packed fp32x2 FMA (Blackwell): d = a*b + d on both 32-bit halves.
__device__ __forceinline__ void fma2(unsigned long long& d,
                                     unsigned long long a,
                                     unsigned long long b) {
    asm("fma.rn.f32x2 %0, %1, %2, %0;" : "+l"(d) : "l"(a), "l"(b));
}
__device__ __forceinline__ unsigned long long pack2(float x, float y) {
    unsigned long long r;
    asm("mov.b64 %0, {%1, %2};" : "=l"(r) : "f"(x), "f"(y));
    return r;
}
__device__ __forceinline__ float2 unpack2(unsigned long long u) {
    float2 r;
    asm("mov.b64 {%0, %1}, %2;" : "=f"(r.x), "=f"(r.y) : "l"(u));
    return r;
}

// 128 threads = 4 warps/block. Each warp handles TWO vertices (half-warp each).
// NO shared memory: weights live in registers and are distributed per-k via
// shfl.sync (SHFL pipe), keeping L1 return bandwidth for the feature gathers.
//
// Phase A: lane l of half h computes the 9 Gaussian weights for ks {l, l+16}
//          of its vertex -> wt[2][9] registers.
// Phase B: lane owns 4 features (f = 4*l..4*l+3). Per 4-k chunk:
//            1 LDG.128  neighbor quad (half-uniform broadcast)
//            4 LDG.128  feature slices (front-batched, MLP=4)
//          per k: 9 SHFL (weights from lane 16h+(k&15)) + packs
//                 + 16 FFMA2 + 4 FFMA.
//          Accumulators pack OFFSET pairs: acc[op][f] = {out[2op][f], out[2op+1][f]}.
// Epilogue: register-half unpack -> 9 STG.128 per vertex.

__global__ void __launch_bounds__(128, 6)
softpixel_kernel(const float* __restrict__ coords,   // [V,4]
                 const float* __restrict__ feats,    // [V,64]
                 const int*   __restrict__ nidx,     // [V,32]
                 const float* __restrict__ lsp,      // [1]
                 float*       __restrict__ out,      // [V,576]
                 int V)
{
    const int warp = threadIdx.x >> 5;
    const int lane = threadIdx.x & 31;
    const int half = lane >> 4;        // which vertex of the pair
    const int l    = lane & 15;

    const int vraw = blockIdx.x * 8 + warp * 2 + half;
    const int v    = vraw < V ? vraw : V - 1;   // clamp: full-warp participation

    const float ls = __ldg(lsp);
    const float a  = -10.0f * ls;      // ACCUMULATE_KNN_EXPONENT
    const float s  = 1.0f / 32.0f;     // fold mean-over-K into weights

    // ---------------- Phase A: weights -> registers -------------------------
    const float4 cv = *reinterpret_cast<const float4*>(coords + 4 * v);

    float wt[2][9];
    #pragma unroll
    for (int t = 0; t < 2; ++t) {
        const int k  = l + 16 * t;
        const int nb = nidx[v * 32 + k];
        const float4 cn = *reinterpret_cast<const float4*>(coords + 4 * nb);
        const float d0 = cv.x - cn.x;
        const float d1 = cv.y - cn.y;
        const float d2 = cv.z - cn.z;
        const float d3 = cv.w - cn.w;
        const float base = d0*d0 + d1*d1 + d2*d2 + d3*d3;
        const float b1 = base + 1.0f;  // ||o||^2 = 1 for the 8 axis offsets

        // Offset order from SoftPixelCNN.create_offsets('onlyaxes', D=4, sub=3):
        // 0:(0,0,0,0) 1:(0,-1,0,0) 2:(-1,0,0,0) 3:(0,0,-1,0) 4:(0,0,0,-1)
        // 5:(0,0,0,+1) 6:(0,0,+1,0) 7:(+1,0,0,0) 8:(0,+1,0,0)
        wt[t][0] = __expf(a * base) * s;
        wt[t][1] = __expf(a * (b1 - 2.0f * d1)) * s;
        wt[t][2] = __expf(a * (b1 - 2.0f * d0)) * s;
        wt[t][3] = __expf(a * (b1 - 2.0f * d2)) * s;
        wt[t][4] = __expf(a * (b1 - 2.0f * d3)) * s;
        wt[t][5] = __expf(a * (b1 + 2.0f * d3)) * s;
        wt[t][6] = __expf(a * (b1 + 2.0f * d2)) * s;
        wt[t][7] = __expf(a * (b1 + 2.0f * d0)) * s;
        wt[t][8] = __expf(a * (b1 + 2.0f * d1)) * s;
    }

    // ---------------- Phase B: accumulate (offset-pair packing) -------------
    // acc[op][f] = packed { out[2*op][f], out[2*op+1][f] }
    unsigned long long acc[4][4];
    float acc8[4];
    #pragma unroll
    for (int op = 0; op < 4; ++op)
        #pragma unroll
        for (int f = 0; f < 4; ++f) acc[op][f] = 0ull;
    #pragma unroll
    for (int f = 0; f < 4; ++f) acc8[f] = 0.0f;

    const int fofs = 4 * l;            // this lane's 4-feature slice
    const int* nrow = nidx + v * 32;
    const int srcbase = 16 * half;     // weight-holder lanes of this half

    #pragma unroll
    for (int k0 = 0; k0 < 32; k0 += 4) {
        // half-uniform neighbor quad: single broadcast LDG.128
        const int4 nb4 = *reinterpret_cast<const int4*>(nrow + k0);

        // front-batched feature loads (MLP = 4 LDG.128)
        float4 g[4];
        g[0] = *reinterpret_cast<const float4*>(feats + nb4.x * 64 + fofs);
        g[1] = *reinterpret_cast<const float4*>(feats + nb4.y * 64 + fofs);
        g[2] = *reinterpret_cast<const float4*>(feats + nb4.z * 64 + fofs);
        g[3] = *reinterpret_cast<const float4*>(feats + nb4.w * 64 + fofs);

        #pragma unroll
        for (int j = 0; j < 4; ++j) {
            const int k   = k0 + j;
            const int t   = k >> 4;               // compile-time after unroll
            const int src = srcbase + (k & 15);   // uniform within each half

            // broadcast the 9 weights of neighbor k from their holder lane
            const float w0 = __shfl_sync(FULL_MASK, wt[t][0], src);
            const float w1 = __shfl_sync(FULL_MASK, wt[t][1], src);
            const float w2 = __shfl_sync(FULL_MASK, wt[t][2], src);
            const float w3 = __shfl_sync(FULL_MASK, wt[t][3], src);
            const float w4 = __shfl_sync(FULL_MASK, wt[t][4], src);
            const float w5 = __shfl_sync(FULL_MASK, wt[t][5], src);
            const float w6 = __shfl_sync(FULL_MASK, wt[t][6], src);
            const float w7 = __shfl_sync(FULL_MASK, wt[t][7], src);
            const float w8 = __shfl_sync(FULL_MASK, wt[t][8], src);

            const unsigned long long w01 = pack2(w0, w1);
            const unsigned long long w23 = pack2(w2, w3);
            const unsigned long long w45 = pack2(w4, w5);
            const unsigned long long w67 = pack2(w6, w7);

            const unsigned long long gd0 = pack2(g[j].x, g[j].x);
            const unsigned long long gd1 = pack2(g[j].y, g[j].y);
            const unsigned long long gd2 = pack2(g[j].z, g[j].z);
            const unsigned long long gd3 = pack2(g[j].w, g[j].w);

            fma2(acc[0][0], w01, gd0); fma2(acc[0][1], w01, gd1);
            fma2(acc[0][2], w01, gd2); fma2(acc[0][3], w01, gd3);
            fma2(acc[1][0], w23, gd0); fma2(acc[1][1], w23, gd1);
            fma2(acc[1][2], w23, gd2); fma2(acc[1][3], w23, gd3);
            fma2(acc[2][0], w45, gd0); fma2(acc[2][1], w45, gd1);
            fma2(acc[2][2], w45, gd2); fma2(acc[2][3], w45, gd3);
            fma2(acc[3][0], w67, gd0); fma2(acc[3][1], w67, gd1);
            fma2(acc[3][2], w67, gd2); fma2(acc[3][3], w67, gd3);

            acc8[0] = fmaf(w8, g[j].x, acc8[0]);
            acc8[1] = fmaf(w8, g[j].y, acc8[1]);
            acc8[2] = fmaf(w8, g[j].z, acc8[2]);
            acc8[3] = fmaf(w8, g[j].w, acc8[3]);
        }
    }

    // ---------------- Epilogue: unpack offset-pairs, vector stores ----------
    float* orow = out + (long long)v * 576 + fofs;
    #pragma unroll
    for (int op = 0; op < 4; ++op) {
        const float2 p0 = unpack2(acc[op][0]);
        const float2 p1 = unpack2(acc[op][1]);
        const float2 p2 = unpack2(acc[op][2]);
        const float2 p3 = unpack2(acc[op][3]);
        *reinterpret_cast<float4*>(orow + (2*op    ) * 64) =
            make_float4(p0.x, p1.x, p2.x, p3.x);
        *reinterpret_cast<float4*>(orow + (2*op + 1) * 64) =
            make_float4(p0.y, p1.y, p2.y, p3.y);
    }
    *reinterpret_cast<float4*>(orow + 8 * 64) =
        make_float4(acc8[0], acc8[1], acc8[2], acc8[3]);
}

extern "C" void kernel_launch(void* const* d_in, const int* in_sizes, int n_in,
                              void* d_out, int out_size) {
    const float* coords = (const float*)d_in[0];   // [V,4]
    const float* feats  = (const float*)d_in[1];   // [V,64]
    // d_in[2] = distsq — unused on the inference path (stop_gradient EMA input)
    const int*   nidx   = (const int*)d_in[3];     // [V,32]
    const float* lsp    = (const float*)d_in[4];   // [1]
    float* out = (float*)d_out;

    const int V = in_sizes[0] / 4;
    const int blocks = (V + 7) / 8;                // 8 vertices per 128-thread block
    softpixel_kernel<<<blocks, 128>>>(coords, feats, nidx, lsp, out, V);
}

// round 9
// speedup vs baseline: 1.2591x; 1.2591x over previous
#include <cuda_runtime.h>

// Packed fp32x2 FMA (Blackwell): d = a*b + d on both 32-bit halves.
__device__ __forceinline__ void fma2(unsigned long long& d,
                                     unsigned long long a,
                                     unsigned long long b) {
    asm("fma.rn.f32x2 %0, %1, %2, %0;" : "+l"(d) : "l"(a), "l"(b));
}
__device__ __forceinline__ unsigned long long pack2(float x, float y) {
    unsigned long long r;
    asm("mov.b64 %0, {%1, %2};" : "=l"(r) : "f"(x), "f"(y));
    return r;
}
__device__ __forceinline__ float2 unpack2(unsigned long long u) {
    float2 r;
    asm("mov.b64 {%0, %1}, %2;" : "=f"(r.x), "=f"(r.y) : "l"(u));
    return r;
}

// 128 threads = 4 warps/block, __launch_bounds__(128, 8): regs capped at 64 so
// 8 blocks (32 warps) fit per SM -> 50% occupancy to cover the L2-hit gathers.
// Each warp handles TWO vertices (half-warp each).
// Phase A: lane computes 9 weights for ks {l, l+16} of its vertex, stores them
//          UN-duplicated (9 floats, row padded to 12 for 16B alignment).
// Phase B: lane owns 4 features (f = 4*l..4*l+3). Per k:
//            2 LDS.128 + 1 LDS.32   (weights w0..w8, natural pairs)
//            1 LDG.128              (feature slice, coalesced 256B/half)
//            4 mov.b64 dups {g,g}   (ALU)
//            16 FFMA2 (offset-pairs) + 4 FFMA (offset 8)
//          Accumulators pack OFFSET pairs: acc[op][f] = {out[2op][f], out[2op+1][f]}.
// Epilogue: free register-half unpack -> 9 STG.128 per vertex.

static constexpr int WROW    = 12;             // 9 weights + 3 pad (floats, 48B row)
static constexpr int HSTRIDE = 32 * WROW + 4;  // +16B: shifts the second half-warp's
                                               // broadcast reads by 4 banks

__global__ void __launch_bounds__(128, 8)
softpixel_kernel(const float* __restrict__ coords,   // [V,4]
                 const float* __restrict__ feats,    // [V,64]
                 const int*   __restrict__ nidx,     // [V,32]
                 const float* __restrict__ lsp,      // [1]
                 float*       __restrict__ out,      // [V,576]
                 int V)
{
    __shared__ __align__(16) float wsm[4][2 * HSTRIDE];   // ~12.1 KB/block

    const int warp = threadIdx.x >> 5;
    const int lane = threadIdx.x & 31;
    const int half = lane >> 4;        // which vertex of the pair
    const int l    = lane & 15;

    const int vraw = blockIdx.x * 8 + warp * 2 + half;
    const int v    = vraw < V ? vraw : V - 1;   // clamp: full-warp participation

    const float ls = __ldg(lsp);
    const float a  = -10.0f * ls;      // ACCUMULATE_KNN_EXPONENT
    const float s  = 1.0f / 32.0f;     // fold mean-over-K into weights

    float* wv = &wsm[warp][half * HSTRIDE];

    // ---------------- Phase A: weights (un-duplicated) ----------------------
    const float4 cv = *reinterpret_cast<const float4*>(coords + 4 * v);

    #pragma unroll
    for (int t = 0; t < 2; ++t) {
        const int k  = l + 16 * t;
        const int nb = nidx[v * 32 + k];
        const float4 cn = *reinterpret_cast<const float4*>(coords + 4 * nb);
        const float d0 = cv.x - cn.x;
        const float d1 = cv.y - cn.y;
        const float d2 = cv.z - cn.z;
        const float d3 = cv.w - cn.w;
        const float base = d0*d0 + d1*d1 + d2*d2 + d3*d3;
        const float b1 = base + 1.0f;  // ||o||^2 = 1 for the 8 axis offsets

        // Offset order from SoftPixelCNN.create_offsets('onlyaxes', D=4, sub=3):
        // 0:(0,0,0,0) 1:(0,-1,0,0) 2:(-1,0,0,0) 3:(0,0,-1,0) 4:(0,0,0,-1)
        // 5:(0,0,0,+1) 6:(0,0,+1,0) 7:(+1,0,0,0) 8:(0,+1,0,0)
        const float w0 = __expf(a * base) * s;
        const float w1 = __expf(a * (b1 - 2.0f * d1)) * s;
        const float w2 = __expf(a * (b1 - 2.0f * d0)) * s;
        const float w3 = __expf(a * (b1 - 2.0f * d2)) * s;
        const float w4 = __expf(a * (b1 - 2.0f * d3)) * s;
        const float w5 = __expf(a * (b1 + 2.0f * d3)) * s;
        const float w6 = __expf(a * (b1 + 2.0f * d2)) * s;
        const float w7 = __expf(a * (b1 + 2.0f * d0)) * s;
        const float w8 = __expf(a * (b1 + 2.0f * d1)) * s;

        float4* dst = reinterpret_cast<float4*>(wv + k * WROW);  // 48B rows, 16B-aligned
        dst[0] = make_float4(w0, w1, w2, w3);
        dst[1] = make_float4(w4, w5, w6, w7);
        wv[k * WROW + 8] = w8;
    }
    __syncwarp();

    // ---------------- Phase B: accumulate (offset-pair packing) -------------
    // acc[op][f] = packed { out[2*op][f], out[2*op+1][f] }
    unsigned long long acc[4][4];
    float acc8[4];
    #pragma unroll
    for (int op = 0; op < 4; ++op)
        #pragma unroll
        for (int f = 0; f < 4; ++f) acc[op][f] = 0ull;
    #pragma unroll
    for (int f = 0; f < 4; ++f) acc8[f] = 0.0f;

    const int fofs = 4 * l;            // this lane's 4-feature slice
    const int* nrow = nidx + v * 32;

    #pragma unroll
    for (int k0 = 0; k0 < 32; k0 += 4) {
        // half-uniform neighbor quad: single broadcast LDG.128
        const int4 nb4 = *reinterpret_cast<const int4*>(nrow + k0);

        // front-batched feature loads (MLP = 4 LDG.128)
        float4 g[4];
        g[0] = *reinterpret_cast<const float4*>(feats + nb4.x * 64 + fofs);
        g[1] = *reinterpret_cast<const float4*>(feats + nb4.y * 64 + fofs);
        g[2] = *reinterpret_cast<const float4*>(feats + nb4.z * 64 + fofs);
        g[3] = *reinterpret_cast<const float4*>(feats + nb4.w * 64 + fofs);

        #pragma unroll
        for (int j = 0; j < 4; ++j) {
            const int k = k0 + j;
            const float4* wr = reinterpret_cast<const float4*>(wv + k * WROW);
            const float4 wA = wr[0];                 // w0 w1 w2 w3
            const float4 wB = wr[1];                 // w4 w5 w6 w7
            const float  w8 = wv[k * WROW + 8];

            const unsigned long long w01 = pack2(wA.x, wA.y);
            const unsigned long long w23 = pack2(wA.z, wA.w);
            const unsigned long long w45 = pack2(wB.x, wB.y);
            const unsigned long long w67 = pack2(wB.z, wB.w);

            const unsigned long long gd0 = pack2(g[j].x, g[j].x);
            const unsigned long long gd1 = pack2(g[j].y, g[j].y);
            const unsigned long long gd2 = pack2(g[j].z, g[j].z);
            const unsigned long long gd3 = pack2(g[j].w, g[j].w);

            fma2(acc[0][0], w01, gd0); fma2(acc[0][1], w01, gd1);
            fma2(acc[0][2], w01, gd2); fma2(acc[0][3], w01, gd3);
            fma2(acc[1][0], w23, gd0); fma2(acc[1][1], w23, gd1);
            fma2(acc[1][2], w23, gd2); fma2(acc[1][3], w23, gd3);
            fma2(acc[2][0], w45, gd0); fma2(acc[2][1], w45, gd1);
            fma2(acc[2][2], w45, gd2); fma2(acc[2][3], w45, gd3);
            fma2(acc[3][0], w67, gd0); fma2(acc[3][1], w67, gd1);
            fma2(acc[3][2], w67, gd2); fma2(acc[3][3], w67, gd3);

            acc8[0] = fmaf(w8, g[j].x, acc8[0]);
            acc8[1] = fmaf(w8, g[j].y, acc8[1]);
            acc8[2] = fmaf(w8, g[j].z, acc8[2]);
            acc8[3] = fmaf(w8, g[j].w, acc8[3]);
        }
    }

    // ---------------- Epilogue: unpack offset-pairs, vector stores ----------
    float* orow = out + (long long)v * 576 + fofs;
    #pragma unroll
    for (int op = 0; op < 4; ++op) {
        const float2 p0 = unpack2(acc[op][0]);
        const float2 p1 = unpack2(acc[op][1]);
        const float2 p2 = unpack2(acc[op][2]);
        const float2 p3 = unpack2(acc[op][3]);
        *reinterpret_cast<float4*>(orow + (2*op    ) * 64) =
            make_float4(p0.x, p1.x, p2.x, p3.x);
        *reinterpret_cast<float4*>(orow + (2*op + 1) * 64) =
            make_float4(p0.y, p1.y, p2.y, p3.y);
    }
    *reinterpret_cast<float4*>(orow + 8 * 64) =
        make_float4(acc8[0], acc8[1], acc8[2], acc8[3]);
}

extern "C" void kernel_launch(void* const* d_in, const int* in_sizes, int n_in,
                              void* d_out, int out_size) {
    const float* coords = (const float*)d_in[0];   // [V,4]
    const float* feats  = (const float*)d_in[1];   // [V,64]
    // d_in[2] = distsq — unused on the inference path (stop_gradient EMA input)
    const int*   nidx   = (const int*)d_in[3];     // [V,32]
    const float* lsp    = (const float*)d_in[4];   // [1]
    float* out = (float*)d_out;

    const int V = in_sizes[0] / 4;
    const int blocks = (V + 7) / 8;                // 8 vertices per 128-thread block
    softpixel_kernel<<<blocks, 128>>>(coords, feats, nidx, lsp, out, V);
}

// round 11
// speedup vs baseline: 1.3091x; 1.0397x over previous
#include <cuda_runtime.h>

// Packed fp32x2 FMA (Blackwell): d = a*b + d on both 32-bit halves.
__device__ __forceinline__ void fma2(unsigned long long& d,
                                     unsigned long long a,
                                     unsigned long long b) {
    asm("fma.rn.f32x2 %0, %1, %2, %0;" : "+l"(d) : "l"(a), "l"(b));
}
__device__ __forceinline__ unsigned long long pack2(float x, float y) {
    unsigned long long r;
    asm("mov.b64 %0, {%1, %2};" : "=l"(r) : "f"(x), "f"(y));
    return r;
}
__device__ __forceinline__ float2 unpack2(unsigned long long u) {
    float2 r;
    asm("mov.b64 {%0, %1}, %2;" : "=f"(r.x), "=f"(r.y) : "l"(u));
    return r;
}

// 128 threads = 4 warps/block. Each warp handles TWO vertices (half-warp each).
// R9 core + SOFTWARE PIPELINING: chunk c+1's neighbor quad and feature rows are
// prefetched while chunk c computes, moving the LDG->use distance to a full
// chunk (~240 issue cycles) so L2-hit gather latency is hidden in-warp.
//
// Phase A: lane computes 9 weights for ks {l, l+16} of its vertex, stores them
//          UN-duplicated (9 floats, row padded to 12 for 16B alignment).
// Phase B: lane owns 4 features (f = 4*l..4*l+3). Per k:
//            2 LDS.128 + 1 LDS.32   (weights w0..w8)
//            4 mov.b64 dups {g,g}   (ALU)
//            16 FFMA2 (offset-pairs) + 4 FFMA (offset 8)
//          Accumulators pack OFFSET pairs: acc[op][f] = {out[2op][f], out[2op+1][f]}.
// Epilogue: register-half unpack -> 9 STG.128 per vertex.

static constexpr int WROW    = 12;             // 9 weights + 3 pad (floats, 48B row)
static constexpr int HSTRIDE = 32 * WROW + 4;  // +16B: shifts the second half-warp's
                                               // broadcast reads by 4 banks

__global__ void __launch_bounds__(128, 6)
softpixel_kernel(const float* __restrict__ coords,   // [V,4]
                 const float* __restrict__ feats,    // [V,64]
                 const int*   __restrict__ nidx,     // [V,32]
                 const float* __restrict__ lsp,      // [1]
                 float*       __restrict__ out,      // [V,576]
                 int V)
{
    __shared__ __align__(16) float wsm[4][2 * HSTRIDE];   // ~12.1 KB/block

    const int warp = threadIdx.x >> 5;
    const int lane = threadIdx.x & 31;
    const int half = lane >> 4;        // which vertex of the pair
    const int l    = lane & 15;

    const int vraw = blockIdx.x * 8 + warp * 2 + half;
    const int v    = vraw < V ? vraw : V - 1;   // clamp: full-warp participation

    const float ls = __ldg(lsp);
    const float a  = -10.0f * ls;      // ACCUMULATE_KNN_EXPONENT
    const float s  = 1.0f / 32.0f;     // fold mean-over-K into weights

    float* wv = &wsm[warp][half * HSTRIDE];

    // ---------------- Phase A: weights (un-duplicated) ----------------------
    const float4 cv = *reinterpret_cast<const float4*>(coords + 4 * v);

    #pragma unroll
    for (int t = 0; t < 2; ++t) {
        const int k  = l + 16 * t;
        const int nb = nidx[v * 32 + k];
        const float4 cn = *reinterpret_cast<const float4*>(coords + 4 * nb);
        const float d0 = cv.x - cn.x;
        const float d1 = cv.y - cn.y;
        const float d2 = cv.z - cn.z;
        const float d3 = cv.w - cn.w;
        const float base = d0*d0 + d1*d1 + d2*d2 + d3*d3;
        const float b1 = base + 1.0f;  // ||o||^2 = 1 for the 8 axis offsets

        // Offset order from SoftPixelCNN.create_offsets('onlyaxes', D=4, sub=3):
        // 0:(0,0,0,0) 1:(0,-1,0,0) 2:(-1,0,0,0) 3:(0,0,-1,0) 4:(0,0,0,-1)
        // 5:(0,0,0,+1) 6:(0,0,+1,0) 7:(+1,0,0,0) 8:(0,+1,0,0)
        const float w0 = __expf(a * base) * s;
        const float w1 = __expf(a * (b1 - 2.0f * d1)) * s;
        const float w2 = __expf(a * (b1 - 2.0f * d0)) * s;
        const float w3 = __expf(a * (b1 - 2.0f * d2)) * s;
        const float w4 = __expf(a * (b1 - 2.0f * d3)) * s;
        const float w5 = __expf(a * (b1 + 2.0f * d3)) * s;
        const float w6 = __expf(a * (b1 + 2.0f * d2)) * s;
        const float w7 = __expf(a * (b1 + 2.0f * d0)) * s;
        const float w8 = __expf(a * (b1 + 2.0f * d1)) * s;

        float4* dst = reinterpret_cast<float4*>(wv + k * WROW);  // 48B rows, 16B-aligned
        dst[0] = make_float4(w0, w1, w2, w3);
        dst[1] = make_float4(w4, w5, w6, w7);
        wv[k * WROW + 8] = w8;
    }
    __syncwarp();

    // ---------------- Phase B: pipelined accumulate (offset-pair packing) ---
    // acc[op][f] = packed { out[2*op][f], out[2*op+1][f] }
    unsigned long long acc[4][4];
    float acc8[4];
    #pragma unroll
    for (int op = 0; op < 4; ++op)
        #pragma unroll
        for (int f = 0; f < 4; ++f) acc[op][f] = 0ull;
    #pragma unroll
    for (int f = 0; f < 4; ++f) acc8[f] = 0.0f;

    const int fofs = 4 * l;            // this lane's 4-feature slice
    const int* nrow = nidx + v * 32;

    // Prologue: load chunk 0
    int4 nb4 = *reinterpret_cast<const int4*>(nrow);
    float4 g[4];
    g[0] = *reinterpret_cast<const float4*>(feats + nb4.x * 64 + fofs);
    g[1] = *reinterpret_cast<const float4*>(feats + nb4.y * 64 + fofs);
    g[2] = *reinterpret_cast<const float4*>(feats + nb4.z * 64 + fofs);
    g[3] = *reinterpret_cast<const float4*>(feats + nb4.w * 64 + fofs);

    #pragma unroll
    for (int c = 0; c < 8; ++c) {
        const int k0 = c * 4;

        // Prefetch chunk c+1 (indices then features) before computing chunk c.
        int4 nb4n;
        float4 gn[4];
        if (c < 7) {
            nb4n = *reinterpret_cast<const int4*>(nrow + k0 + 4);
            gn[0] = *reinterpret_cast<const float4*>(feats + nb4n.x * 64 + fofs);
            gn[1] = *reinterpret_cast<const float4*>(feats + nb4n.y * 64 + fofs);
            gn[2] = *reinterpret_cast<const float4*>(feats + nb4n.z * 64 + fofs);
            gn[3] = *reinterpret_cast<const float4*>(feats + nb4n.w * 64 + fofs);
        }

        #pragma unroll
        for (int j = 0; j < 4; ++j) {
            const int k = k0 + j;
            const float4* wr = reinterpret_cast<const float4*>(wv + k * WROW);
            const float4 wA = wr[0];                 // w0 w1 w2 w3
            const float4 wB = wr[1];                 // w4 w5 w6 w7
            const float  w8 = wv[k * WROW + 8];

            const unsigned long long w01 = pack2(wA.x, wA.y);
            const unsigned long long w23 = pack2(wA.z, wA.w);
            const unsigned long long w45 = pack2(wB.x, wB.y);
            const unsigned long long w67 = pack2(wB.z, wB.w);

            const unsigned long long gd0 = pack2(g[j].x, g[j].x);
            const unsigned long long gd1 = pack2(g[j].y, g[j].y);
            const unsigned long long gd2 = pack2(g[j].z, g[j].z);
            const unsigned long long gd3 = pack2(g[j].w, g[j].w);

            fma2(acc[0][0], w01, gd0); fma2(acc[0][1], w01, gd1);
            fma2(acc[0][2], w01, gd2); fma2(acc[0][3], w01, gd3);
            fma2(acc[1][0], w23, gd0); fma2(acc[1][1], w23, gd1);
            fma2(acc[1][2], w23, gd2); fma2(acc[1][3], w23, gd3);
            fma2(acc[2][0], w45, gd0); fma2(acc[2][1], w45, gd1);
            fma2(acc[2][2], w45, gd2); fma2(acc[2][3], w45, gd3);
            fma2(acc[3][0], w67, gd0); fma2(acc[3][1], w67, gd1);
            fma2(acc[3][2], w67, gd2); fma2(acc[3][3], w67, gd3);

            acc8[0] = fmaf(w8, g[j].x, acc8[0]);
            acc8[1] = fmaf(w8, g[j].y, acc8[1]);
            acc8[2] = fmaf(w8, g[j].z, acc8[2]);
            acc8[3] = fmaf(w8, g[j].w, acc8[3]);
        }

        // Rotate buffers (register renaming after full unroll — no MOVs)
        if (c < 7) {
            nb4 = nb4n;
            g[0] = gn[0]; g[1] = gn[1]; g[2] = gn[2]; g[3] = gn[3];
        }
    }

    // ---------------- Epilogue: unpack offset-pairs, vector stores ----------
    float* orow = out + (long long)v * 576 + fofs;
    #pragma unroll
    for (int op = 0; op < 4; ++op) {
        const float2 p0 = unpack2(acc[op][0]);
        const float2 p1 = unpack2(acc[op][1]);
        const float2 p2 = unpack2(acc[op][2]);
        const float2 p3 = unpack2(acc[op][3]);
        *reinterpret_cast<float4*>(orow + (2*op    ) * 64) =
            make_float4(p0.x, p1.x, p2.x, p3.x);
        *reinterpret_cast<float4*>(orow + (2*op + 1) * 64) =
            make_float4(p0.y, p1.y, p2.y, p3.y);
    }
    *reinterpret_cast<float4*>(orow + 8 * 64) =
        make_float4(acc8[0], acc8[1], acc8[2], acc8[3]);
}

extern "C" void kernel_launch(void* const* d_in, const int* in_sizes, int n_in,
                              void* d_out, int out_size) {
    const float* coords = (const float*)d_in[0];   // [V,4]
    const float* feats  = (const float*)d_in[1];   // [V,64]
    // d_in[2] = distsq — unused on the inference path (stop_gradient EMA input)
    const int*   nidx   = (const int*)d_in[3];     // [V,32]
    const float* lsp    = (const float*)d_in[4];   // [1]
    float* out = (float*)d_out;

    const int V = in_sizes[0] / 4;
    const int blocks = (V + 7) / 8;                // 8 vertices per 128-thread block
    softpixel_kernel<<<blocks, 128>>>(coords, feats, nidx, lsp, out, V);
}